// round 1
// baseline (speedup 1.0000x reference)
#include <cuda_runtime.h>
#include <math.h>
#include <stdint.h>

// Problem constants
#define DDIM 1024
#define NEXP 8
#define HDIM 4096
#define TOPK 2
#define NTOK 8192               // B*S = 4*2048
#define NROWS (NTOK * TOPK)     // 16384

// Tiling
#define BM 128
#define BN 128
#define BK 16

// ---------------- scratch (device globals; no allocation allowed) -------------
__device__ float g_h[(size_t)NROWS * HDIM];     // GEMM1 output (post-GELU), grouped row order
__device__ float g_oscr[(size_t)NROWS * DDIM];  // GEMM2 output, indexed by (token*2+k) slot
__device__ int   g_rows_token[NROWS];           // grouped row -> token id
__device__ int   g_rows_dest[NROWS];            // grouped row -> slot (token*2+k)
__device__ float g_wslot[NROWS];                // gate weight per slot (token*2+k)
__device__ int   g_tok_eidx[NROWS];             // expert index per slot
__device__ int   g_counts[NEXP];
__device__ int   g_offsets[NEXP + 1];
__device__ int   g_fill[NEXP];

// ---------------- gating ------------------------------------------------------
__global__ void reset_kernel() {
    int i = threadIdx.x;
    if (i < NEXP) g_counts[i] = 0;
}

// One warp per token: scores = x[t] @ gate_w  (D x E), then top-2 + softmax.
__global__ void gate_kernel(const float* __restrict__ x, const float* __restrict__ gw) {
    int warp = (blockIdx.x * blockDim.x + threadIdx.x) >> 5;
    int lane = threadIdx.x & 31;
    if (warp >= NTOK) return;
    const float* xr = x + (size_t)warp * DDIM;

    float acc[NEXP];
#pragma unroll
    for (int e = 0; e < NEXP; e++) acc[e] = 0.f;

    for (int d = lane; d < DDIM; d += 32) {
        float xv = xr[d];
        const float* g = gw + (size_t)d * NEXP;
#pragma unroll
        for (int e = 0; e < NEXP; e++) acc[e] = fmaf(xv, g[e], acc[e]);
    }
#pragma unroll
    for (int e = 0; e < NEXP; e++) {
#pragma unroll
        for (int o = 16; o > 0; o >>= 1)
            acc[e] += __shfl_xor_sync(0xffffffff, acc[e], o);
    }
    if (lane == 0) {
        // top-1 (ties -> lowest index, matches jax.lax.top_k)
        int b0 = 0; float s0 = acc[0];
#pragma unroll
        for (int e = 1; e < NEXP; e++) if (acc[e] > s0) { s0 = acc[e]; b0 = e; }
        // top-2
        int b1 = -1; float s1 = -INFINITY;
#pragma unroll
        for (int e = 0; e < NEXP; e++)
            if (e != b0 && acc[e] > s1) { s1 = acc[e]; b1 = e; }
        // softmax over [s0, s1] with s0 >= s1
        float p = expf(s1 - s0);
        float inv = 1.0f / (1.0f + p);
        g_tok_eidx[warp * 2 + 0] = b0;
        g_tok_eidx[warp * 2 + 1] = b1;
        g_wslot[warp * 2 + 0] = inv;
        g_wslot[warp * 2 + 1] = p * inv;
        atomicAdd(&g_counts[b0], 1);
        atomicAdd(&g_counts[b1], 1);
    }
}

__global__ void scan_kernel() {
    int s = 0;
    for (int e = 0; e < NEXP; e++) {
        g_offsets[e] = s;
        s += g_counts[e];
        g_fill[e] = 0;
    }
    g_offsets[NEXP] = s;
}

__global__ void build_kernel() {
    int t = blockIdx.x * blockDim.x + threadIdx.x;
    if (t >= NTOK) return;
#pragma unroll
    for (int k = 0; k < TOPK; k++) {
        int e = g_tok_eidx[t * 2 + k];
        int pos = g_offsets[e] + atomicAdd(&g_fill[e], 1);
        g_rows_token[pos] = t;
        g_rows_dest[pos] = t * 2 + k;
    }
}

// ---------------- grouped GEMMs ------------------------------------------------
// MODE 1: A = x (gathered by token id), B = w1[e] (D x H), epilogue = +b1, GELU, -> g_h
// MODE 2: A = g_h (contiguous grouped rows), B = w2[e] (H x D), epilogue = +b2, -> g_oscr[slot]
template <int MODE>
__global__ __launch_bounds__(256)
void moe_gemm(const float* __restrict__ Aparam,
              const float* __restrict__ Bmat,
              const float* __restrict__ bias) {
    constexpr int KDIM = (MODE == 1) ? DDIM : HDIM;
    constexpr int NDIM = (MODE == 1) ? HDIM : DDIM;

    int e = blockIdx.z;
    int roff = g_offsets[e];
    int cnt = g_offsets[e + 1] - roff;
    int m0 = blockIdx.y * BM;
    if (m0 >= cnt) return;
    int n0 = blockIdx.x * BN;

    const float* A = (MODE == 1) ? Aparam : g_h;
    const float* Bexp = Bmat + (size_t)e * KDIM * NDIM;
    const float* bexp = bias + (size_t)e * NDIM;

    __shared__ float As[BK][BM];
    __shared__ float Bs[BK][BN];
    __shared__ int rowsrc[BM];

    int tid = threadIdx.x;
    if (tid < BM) {
        int r = m0 + tid;
        int src = -1;
        if (r < cnt) src = (MODE == 1) ? g_rows_token[roff + r] : (roff + r);
        rowsrc[tid] = src;
    }
    __syncthreads();

    float acc[8][8];
#pragma unroll
    for (int i = 0; i < 8; i++)
#pragma unroll
        for (int j = 0; j < 8; j++) acc[i][j] = 0.f;

    int ty = tid >> 4, tx = tid & 15;

    for (int k0 = 0; k0 < KDIM; k0 += BK) {
        // Load A tile (BM x BK), transposed into As[k][m]. 2 passes x float4.
#pragma unroll
        for (int p = 0; p < 2; p++) {
            int row = (tid >> 2) + p * 64;
            int c4 = (tid & 3) * 4;
            int src = rowsrc[row];
            float4 v = make_float4(0.f, 0.f, 0.f, 0.f);
            if (src >= 0)
                v = *reinterpret_cast<const float4*>(A + (size_t)src * KDIM + k0 + c4);
            As[c4 + 0][row] = v.x;
            As[c4 + 1][row] = v.y;
            As[c4 + 2][row] = v.z;
            As[c4 + 3][row] = v.w;
        }
        // Load B tile (BK x BN), coalesced float4.
#pragma unroll
        for (int p = 0; p < 2; p++) {
            int brow = (tid >> 5) + p * 8;
            int bc = (tid & 31) * 4;
            float4 v = *reinterpret_cast<const float4*>(
                Bexp + (size_t)(k0 + brow) * NDIM + n0 + bc);
            *reinterpret_cast<float4*>(&Bs[brow][bc]) = v;
        }
        __syncthreads();

#pragma unroll
        for (int kk = 0; kk < BK; kk++) {
            float a[8], b[8];
#pragma unroll
            for (int i = 0; i < 8; i++) a[i] = As[kk][ty * 8 + i];
#pragma unroll
            for (int j = 0; j < 8; j++) b[j] = Bs[kk][tx * 8 + j];
#pragma unroll
            for (int i = 0; i < 8; i++)
#pragma unroll
                for (int j = 0; j < 8; j++)
                    acc[i][j] = fmaf(a[i], b[j], acc[i][j]);
        }
        __syncthreads();
    }

    // Epilogue
#pragma unroll
    for (int i = 0; i < 8; i++) {
        int r = m0 + ty * 8 + i;
        if (r >= cnt) continue;
        float* crow;
        if (MODE == 1) {
            crow = g_h + (size_t)(roff + r) * NDIM + n0 + tx * 8;
        } else {
            int slot = g_rows_dest[roff + r];
            crow = g_oscr + (size_t)slot * NDIM + n0 + tx * 8;
        }
#pragma unroll
        for (int j = 0; j < 8; j++) {
            float v = acc[i][j] + bexp[n0 + tx * 8 + j];
            if (MODE == 1)
                v = 0.5f * v * (1.0f + erff(v * 0.70710678118654752f));  // exact GELU
            crow[j] = v;
        }
    }
}

// ---------------- combine ------------------------------------------------------
__global__ void combine_kernel(float* __restrict__ y) {
    int idx = blockIdx.x * blockDim.x + threadIdx.x;
    if (idx >= NTOK * DDIM) return;
    int t = idx / DDIM;
    int d = idx - t * DDIM;
    float w0 = g_wslot[t * 2 + 0];
    float w1 = g_wslot[t * 2 + 1];
    float v0 = g_oscr[(size_t)(t * 2 + 0) * DDIM + d];
    float v1 = g_oscr[(size_t)(t * 2 + 1) * DDIM + d];
    y[idx] = fmaf(w0, v0, w1 * v1);
}

// ---------------- launch -------------------------------------------------------
extern "C" void kernel_launch(void* const* d_in, const int* in_sizes, int n_in,
                              void* d_out, int out_size) {
    const float* x  = (const float*)d_in[0];  // [B,S,D]
    const float* gw = (const float*)d_in[1];  // [D,E]
    const float* w1 = (const float*)d_in[2];  // [E,D,H]
    const float* b1 = (const float*)d_in[3];  // [E,H]
    const float* w2 = (const float*)d_in[4];  // [E,H,D]
    const float* b2 = (const float*)d_in[5];  // [E,D]
    float* y = (float*)d_out;                 // [B,S,D] fp32

    reset_kernel<<<1, 32>>>();
    gate_kernel<<<NTOK / 8, 256>>>(x, gw);     // 8 warps/block, 1 token/warp
    scan_kernel<<<1, 1>>>();
    build_kernel<<<NTOK / 256, 256>>>();

    // GEMM1: [rows_e x D] @ [D x H] -> GELU -> g_h
    moe_gemm<1><<<dim3(HDIM / BN, NROWS / BM, NEXP), 256>>>(x, w1, b1);
    // GEMM2: [rows_e x H] @ [H x D] -> +b2 -> g_oscr[slot]
    moe_gemm<2><<<dim3(DDIM / BN, NROWS / BM, NEXP), 256>>>(nullptr, w2, b2);

    combine_kernel<<<(NTOK * DDIM) / 256, 256>>>(y);
}